// round 1
// baseline (speedup 1.0000x reference)
#include <cuda_runtime.h>
#include <cuda_bf16.h>
#include <math.h>

// Problem constants
#define BATCH 2
#define SLEN  4096
#define DMODEL 768
#define NH    12
#define HD    64
#define MROWS (BATCH * SLEN)        // 8192

// ---------------- scratch (device globals; allocation-free) ----------------
__device__ float g_qh[BATCH * NH * SLEN * HD];   // [B,H,S,HD]
__device__ float g_kh[BATCH * NH * SLEN * HD];
__device__ float g_vh[BATCH * NH * SLEN * HD];
__device__ float g_feats[BATCH * SLEN * DMODEL]; // [B,S,D]

// ---------------- SGEMM: C = X @ W^T + bias -------------------------------
// X: [M,K] row-major, W: [N,K] row-major (torch Linear weight), bias: [N]
// mode 0: C[m*N + n]
// mode 1: split heads -> C[((b*NH + h)*SLEN + s)*HD + hd], m=b*SLEN+s, n=h*HD+hd
#define GBM 128
#define GBN 128
#define GBK 8

__global__ __launch_bounds__(256) void sgemm_bias_kernel(
    const float* __restrict__ A, const float* __restrict__ W,
    const float* __restrict__ bias, float* __restrict__ C,
    int M, int N, int K, int mode)
{
    __shared__ float As[GBK][GBM];
    __shared__ float Bs[GBK][GBN];

    const int tid = threadIdx.x;
    const int bm = blockIdx.y * GBM;
    const int bn = blockIdx.x * GBN;

    // Load mapping: 256 threads, each loads one float4 of A and one of W per K-step
    const int lr = tid >> 1;          // 0..127 : row (A) / n (W) within tile
    const int lc = (tid & 1) * 4;     // 0 or 4 : k offset

    const float* Aptr = A + (size_t)(bm + lr) * K + lc;
    const float* Wptr = W + (size_t)(bn + lr) * K + lc;

    float acc[8][8];
    #pragma unroll
    for (int i = 0; i < 8; i++)
        #pragma unroll
        for (int j = 0; j < 8; j++) acc[i][j] = 0.f;

    const int tx = tid & 15;          // n micro
    const int ty = tid >> 4;          // m micro

    for (int k0 = 0; k0 < K; k0 += GBK) {
        float4 av = *(const float4*)(Aptr + k0);
        float4 wv = *(const float4*)(Wptr + k0);
        As[lc + 0][lr] = av.x; As[lc + 1][lr] = av.y;
        As[lc + 2][lr] = av.z; As[lc + 3][lr] = av.w;
        Bs[lc + 0][lr] = wv.x; Bs[lc + 1][lr] = wv.y;
        Bs[lc + 2][lr] = wv.z; Bs[lc + 3][lr] = wv.w;
        __syncthreads();

        #pragma unroll
        for (int kk = 0; kk < GBK; ++kk) {
            float a[8], b[8];
            *(float4*)(a)     = *(const float4*)&As[kk][ty * 8];
            *(float4*)(a + 4) = *(const float4*)&As[kk][ty * 8 + 4];
            *(float4*)(b)     = *(const float4*)&Bs[kk][tx * 8];
            *(float4*)(b + 4) = *(const float4*)&Bs[kk][tx * 8 + 4];
            #pragma unroll
            for (int i = 0; i < 8; i++)
                #pragma unroll
                for (int j = 0; j < 8; j++)
                    acc[i][j] += a[i] * b[j];
        }
        __syncthreads();
    }

    // epilogue
    #pragma unroll
    for (int i = 0; i < 8; i++) {
        const int m = bm + ty * 8 + i;
        #pragma unroll
        for (int j = 0; j < 8; j++) {
            const int n = bn + tx * 8 + j;
            float v = acc[i][j] + bias[n];
            if (mode == 0) {
                C[(size_t)m * N + n] = v;
            } else {
                const int b  = m >> 12;        // / SLEN
                const int s  = m & (SLEN - 1);
                const int h  = n >> 6;         // / HD
                const int hd = n & (HD - 1);
                C[(((size_t)(b * NH + h)) * SLEN + s) * HD + hd] = v;
            }
        }
    }
}

// ---------------- Flash attention (fp32, causal, thread-per-query) --------
// Qh/Kh/Vh: [B,H,S,HD]; feats out: [B,S,D]
__global__ __launch_bounds__(128) void attn_kernel(
    const float* __restrict__ Qh, const float* __restrict__ Kh,
    const float* __restrict__ Vh, float* __restrict__ feats)
{
    __shared__ float Ks[64 * HD];
    __shared__ float Vs[64 * HD];

    const int bh  = blockIdx.y;           // 0..23
    const int q0  = blockIdx.x * 128;
    const int tid = threadIdx.x;
    const int qidx = q0 + tid;

    const size_t base = (size_t)bh * SLEN * HD;
    const float* base_k = Kh + base;
    const float* base_v = Vh + base;

    // load q row, fold in 1/sqrt(HD)
    float4 qreg[16];
    {
        const float4* qp = (const float4*)(Qh + base + (size_t)qidx * HD);
        #pragma unroll
        for (int i = 0; i < 16; i++) {
            float4 t = qp[i];
            t.x *= 0.125f; t.y *= 0.125f; t.z *= 0.125f; t.w *= 0.125f;
            qreg[i] = t;
        }
    }

    float m = -INFINITY, l = 0.f;
    float4 acc[16];
    #pragma unroll
    for (int i = 0; i < 16; i++) acc[i] = make_float4(0.f, 0.f, 0.f, 0.f);

    const int ntiles = q0 / 64 + 2;       // key tiles covering [0, q0+127]

    for (int t = 0; t < ntiles; ++t) {
        const int k0 = t * 64;
        // cooperative linear copy: 64 rows x 64 floats contiguous = 1024 float4
        const float4* srcK = (const float4*)(base_k + (size_t)k0 * HD);
        const float4* srcV = (const float4*)(base_v + (size_t)k0 * HD);
        #pragma unroll
        for (int i = 0; i < 8; i++) {
            const int f = tid + i * 128;
            ((float4*)Ks)[f] = srcK[f];
            ((float4*)Vs)[f] = srcV[f];
        }
        __syncthreads();

        const int jend = min(64, qidx - k0 + 1);   // causal bound (may be <=0)
        for (int j = 0; j < jend; ++j) {
            const float4* kr = (const float4*)(Ks + j * HD);
            float s = 0.f;
            #pragma unroll
            for (int i = 0; i < 16; i++) {
                float4 kv = kr[i];
                s += qreg[i].x * kv.x + qreg[i].y * kv.y
                   + qreg[i].z * kv.z + qreg[i].w * kv.w;
            }
            const float4* vr = (const float4*)(Vs + j * HD);
            if (s <= m) {                       // common path: no rescale
                const float p = __expf(s - m);
                l += p;
                #pragma unroll
                for (int i = 0; i < 16; i++) {
                    float4 vv = vr[i];
                    acc[i].x += p * vv.x; acc[i].y += p * vv.y;
                    acc[i].z += p * vv.z; acc[i].w += p * vv.w;
                }
            } else {                            // new running max (~8x per row)
                const float c = __expf(m - s);
                m = s;
                l = l * c + 1.f;
                #pragma unroll
                for (int i = 0; i < 16; i++) {
                    float4 vv = vr[i];
                    acc[i].x = acc[i].x * c + vv.x;
                    acc[i].y = acc[i].y * c + vv.y;
                    acc[i].z = acc[i].z * c + vv.z;
                    acc[i].w = acc[i].w * c + vv.w;
                }
            }
        }
        __syncthreads();
    }

    const float inv = 1.f / l;
    const int b = bh / NH, h = bh % NH;
    float4* out = (float4*)(feats + ((size_t)(b * SLEN + qidx)) * DMODEL + h * HD);
    #pragma unroll
    for (int i = 0; i < 16; i++) {
        float4 o = acc[i];
        o.x *= inv; o.y *= inv; o.z *= inv; o.w *= inv;
        out[i] = o;
    }
}

// ---------------- launch ---------------------------------------------------
extern "C" void kernel_launch(void* const* d_in, const int* in_sizes, int n_in,
                              void* d_out, int out_size)
{
    const float* q  = (const float*)d_in[0];
    const float* k  = (const float*)d_in[1];
    const float* v  = (const float*)d_in[2];
    // d_in[3] = mask (always causal triu(k=1); handled analytically)
    const float* Wq = (const float*)d_in[4];
    const float* bq = (const float*)d_in[5];
    const float* Wk = (const float*)d_in[6];
    const float* bk = (const float*)d_in[7];
    const float* Wv = (const float*)d_in[8];
    const float* bv = (const float*)d_in[9];
    const float* Wo = (const float*)d_in[10];
    const float* bo = (const float*)d_in[11];

    float *qh, *kh, *vh, *feats;
    cudaGetSymbolAddress((void**)&qh, g_qh);
    cudaGetSymbolAddress((void**)&kh, g_kh);
    cudaGetSymbolAddress((void**)&vh, g_vh);
    cudaGetSymbolAddress((void**)&feats, g_feats);

    dim3 gg(DMODEL / GBN, MROWS / GBM);   // (6, 64)
    sgemm_bias_kernel<<<gg, 256>>>(q, Wq, bq, qh, MROWS, DMODEL, DMODEL, 1);
    sgemm_bias_kernel<<<gg, 256>>>(k, Wk, bk, kh, MROWS, DMODEL, DMODEL, 1);
    sgemm_bias_kernel<<<gg, 256>>>(v, Wv, bv, vh, MROWS, DMODEL, DMODEL, 1);

    attn_kernel<<<dim3(SLEN / 128, BATCH * NH), 128>>>(qh, kh, vh, feats);

    sgemm_bias_kernel<<<gg, 256>>>(feats, Wo, bo, (float*)d_out,
                                   MROWS, DMODEL, DMODEL, 0);
}

// round 4
// speedup vs baseline: 3.0510x; 3.0510x over previous
#include <cuda_runtime.h>
#include <math.h>
#include <stdint.h>

// Problem constants
#define BATCH 2
#define SLEN  4096
#define DMODEL 768
#define NH    12
#define HD    64
#define MROWS (BATCH * SLEN)        // 8192

// ---------------- scratch (device globals; allocation-free) ----------------
__device__ float g_qh[BATCH * NH * SLEN * HD];   // [B,H,S,HD]
__device__ float g_kh[BATCH * NH * SLEN * HD];
__device__ float g_vh[BATCH * NH * SLEN * HD];
__device__ float g_feats[BATCH * SLEN * DMODEL]; // [B,S,D]

// ==================== helpers ====================
__device__ __forceinline__ uint32_t f2tf(float x) {
    uint32_t r;
    asm("cvt.rna.tf32.f32 %0, %1;" : "=r"(r) : "f"(x));
    return r;
}
// D = A(16x8, row) @ B(8x8, col) + D, tf32 inputs, f32 accum
__device__ __forceinline__ void mma8(float* c, const uint32_t* a,
                                     uint32_t b0, uint32_t b1) {
    asm volatile(
        "mma.sync.aligned.m16n8k8.row.col.f32.tf32.tf32.f32 "
        "{%0,%1,%2,%3}, {%4,%5,%6,%7}, {%8,%9}, {%0,%1,%2,%3};"
        : "+f"(c[0]), "+f"(c[1]), "+f"(c[2]), "+f"(c[3])
        : "r"(a[0]), "r"(a[1]), "r"(a[2]), "r"(a[3]), "r"(b0), "r"(b1));
}

// ==================== tf32 mma.sync GEMM: C = X @ W^T + bias ====================
#define TBK 32
#define APITCH 36
#define STAGE_WORDS (128 * APITCH)                 // 4608 words
#define GEMM_SMEM (4 * STAGE_WORDS * 4)            // 73728 B

__global__ __launch_bounds__(256)
void mma_gemm_kernel(const float* __restrict__ A, const float* __restrict__ W,
                     const float* __restrict__ bias, float* __restrict__ C, int mode)
{
    extern __shared__ uint32_t sm[];
    uint32_t* AsBase = sm;                       // [2][STAGE_WORDS]
    uint32_t* BsBase = sm + 2 * STAGE_WORDS;     // [2][STAGE_WORDS]

    const int tid  = threadIdx.x;
    const int lane = tid & 31, wid = tid >> 5;
    const int g = lane >> 2, tig = lane & 3;
    const int wm = wid >> 2, wn = wid & 3;       // 2 x 4 warp grid
    const int bm = blockIdx.y * 128, bn = blockIdx.x * 128;

    const int lr = tid >> 3;                     // 0..31
    const int lc = (tid & 7) * 4;                // 0,4,...,28
    const float* Ap = A + (size_t)(bm + lr) * DMODEL + lc;
    const float* Wp = W + (size_t)(bn + lr) * DMODEL + lc;

    float acc[4][4][4];
    #pragma unroll
    for (int i = 0; i < 4; i++)
        #pragma unroll
        for (int j = 0; j < 4; j++)
            #pragma unroll
            for (int t = 0; t < 4; t++) acc[i][j][t] = 0.f;

    float4 ra[4], rb[4];
    #pragma unroll
    for (int i = 0; i < 4; i++) {
        ra[i] = *(const float4*)(Ap + (size_t)i * 32 * DMODEL);
        rb[i] = *(const float4*)(Wp + (size_t)i * 32 * DMODEL);
    }
    #pragma unroll
    for (int i = 0; i < 4; i++) {
        const uint32_t idx = (uint32_t)(lr + 32 * i) * APITCH + lc;
        *(uint4*)&AsBase[idx] = make_uint4(f2tf(ra[i].x), f2tf(ra[i].y), f2tf(ra[i].z), f2tf(ra[i].w));
        *(uint4*)&BsBase[idx] = make_uint4(f2tf(rb[i].x), f2tf(rb[i].y), f2tf(rb[i].z), f2tf(rb[i].w));
    }
    __syncthreads();

    const int KT = DMODEL / TBK;                 // 24
    for (int kt = 0; kt < KT; kt++) {
        const int s = kt & 1;
        const uint32_t* Sa = AsBase + s * STAGE_WORDS;
        const uint32_t* Sb = BsBase + s * STAGE_WORDS;

        if (kt + 1 < KT) {
            const float* ap = Ap + (size_t)(kt + 1) * TBK;
            const float* wp = Wp + (size_t)(kt + 1) * TBK;
            #pragma unroll
            for (int i = 0; i < 4; i++) {
                ra[i] = *(const float4*)(ap + (size_t)i * 32 * DMODEL);
                rb[i] = *(const float4*)(wp + (size_t)i * 32 * DMODEL);
            }
        }

        #pragma unroll
        for (int kk = 0; kk < 4; kk++) {
            const int k0 = kk * 8;
            uint32_t af[4][4];
            #pragma unroll
            for (int mf = 0; mf < 4; mf++) {
                const uint32_t* bp = Sa + (uint32_t)(wm * 64 + mf * 16) * APITCH + k0;
                af[mf][0] = bp[(uint32_t)g * APITCH + tig];
                af[mf][1] = bp[(uint32_t)(g + 8) * APITCH + tig];
                af[mf][2] = bp[(uint32_t)g * APITCH + tig + 4];
                af[mf][3] = bp[(uint32_t)(g + 8) * APITCH + tig + 4];
            }
            uint32_t bf[4][2];
            #pragma unroll
            for (int nf = 0; nf < 4; nf++) {
                const uint32_t* bp = Sb + (uint32_t)(wn * 32 + nf * 8 + g) * APITCH + k0;
                bf[nf][0] = bp[tig];
                bf[nf][1] = bp[tig + 4];
            }
            #pragma unroll
            for (int mf = 0; mf < 4; mf++)
                #pragma unroll
                for (int nf = 0; nf < 4; nf++)
                    mma8(acc[mf][nf], af[mf], bf[nf][0], bf[nf][1]);
        }

        if (kt + 1 < KT) {
            __syncthreads();
            const int s1 = s ^ 1;
            #pragma unroll
            for (int i = 0; i < 4; i++) {
                const uint32_t idx = (uint32_t)(lr + 32 * i) * APITCH + lc;
                *(uint4*)&AsBase[s1 * STAGE_WORDS + idx] =
                    make_uint4(f2tf(ra[i].x), f2tf(ra[i].y), f2tf(ra[i].z), f2tf(ra[i].w));
                *(uint4*)&BsBase[s1 * STAGE_WORDS + idx] =
                    make_uint4(f2tf(rb[i].x), f2tf(rb[i].y), f2tf(rb[i].z), f2tf(rb[i].w));
            }
            __syncthreads();
        }
    }

    // epilogue
    #pragma unroll
    for (int mf = 0; mf < 4; mf++) {
        const int r0 = bm + wm * 64 + mf * 16 + g;
        #pragma unroll
        for (int nf = 0; nf < 4; nf++) {
            const int c = bn + wn * 32 + nf * 8 + tig * 2;
            const float b0 = bias[c], b1 = bias[c + 1];
            float2 v0 = make_float2(acc[mf][nf][0] + b0, acc[mf][nf][1] + b1);
            float2 v1 = make_float2(acc[mf][nf][2] + b0, acc[mf][nf][3] + b1);
            if (mode == 0) {
                *(float2*)(C + (size_t)r0 * DMODEL + c) = v0;
                *(float2*)(C + (size_t)(r0 + 8) * DMODEL + c) = v1;
            } else {
                const int h = c >> 6, hd = c & (HD - 1);
                const int bb0 = r0 >> 12, s0r = r0 & (SLEN - 1);
                *(float2*)(C + (((size_t)(bb0 * NH + h)) * SLEN + s0r) * HD + hd) = v0;
                const int r1 = r0 + 8;
                const int bb1 = r1 >> 12, s1r = r1 & (SLEN - 1);
                *(float2*)(C + (((size_t)(bb1 * NH + h)) * SLEN + s1r) * HD + hd) = v1;
            }
        }
    }
}

// ==================== flash attention with mma.sync (tf32) ====================
#define QPITCH 68
#define KPITCH 68
#define VPITCH 69
#define QS_OFF 0
#define KS_OFF (64 * QPITCH)
#define VT_OFF (KS_OFF + 64 * KPITCH)
#define ATT_SMEM_BYTES ((VT_OFF + 64 * VPITCH) * 4)   // 52480

__global__ __launch_bounds__(128)
void attn_mma_kernel(const float* __restrict__ Qh, const float* __restrict__ Kh,
                     const float* __restrict__ Vh, float* __restrict__ feats)
{
    extern __shared__ uint32_t sm[];
    const int tid = threadIdx.x, lane = tid & 31, w = tid >> 5;
    const int g = lane >> 2, tig = lane & 3;
    const int bh = blockIdx.y, qt = blockIdx.x;
    const int q0 = qt * 64;
    const int b = bh / NH, h = bh % NH;
    const size_t base = (size_t)bh * SLEN * HD;
    const int m0 = w * 16;

    {
        const int r = tid >> 1;
        const int cb = (tid & 1) * 32;
        const float4* src = (const float4*)(Qh + base + (size_t)(q0 + r) * HD + cb);
        #pragma unroll
        for (int i = 0; i < 8; i++) {
            float4 t = src[i];
            *(uint4*)&sm[QS_OFF + (uint32_t)r * QPITCH + cb + i * 4] =
                make_uint4(f2tf(t.x * 0.125f), f2tf(t.y * 0.125f),
                           f2tf(t.z * 0.125f), f2tf(t.w * 0.125f));
        }
    }
    __syncthreads();

    uint32_t qa[8][4];
    #pragma unroll
    for (int kf = 0; kf < 8; kf++) {
        qa[kf][0] = sm[QS_OFF + (uint32_t)(m0 + g) * QPITCH + kf * 8 + tig];
        qa[kf][1] = sm[QS_OFF + (uint32_t)(m0 + g + 8) * QPITCH + kf * 8 + tig];
        qa[kf][2] = sm[QS_OFF + (uint32_t)(m0 + g) * QPITCH + kf * 8 + tig + 4];
        qa[kf][3] = sm[QS_OFF + (uint32_t)(m0 + g + 8) * QPITCH + kf * 8 + tig + 4];
    }

    float o[8][4];
    #pragma unroll
    for (int i = 0; i < 8; i++)
        #pragma unroll
        for (int t = 0; t < 4; t++) o[i][t] = 0.f;
    float l0 = 0.f, l1 = 0.f, mr0 = -INFINITY, mr1 = -INFINITY;

    for (int kt = 0; kt <= qt; kt++) {
        const int k0 = kt * 64;
        {
            const int r = tid >> 1;
            const int cb = (tid & 1) * 32;
            const float4* src = (const float4*)(Kh + base + (size_t)(k0 + r) * HD + cb);
            #pragma unroll
            for (int i = 0; i < 8; i++) {
                float4 t = src[i];
                *(uint4*)&sm[KS_OFF + (uint32_t)r * KPITCH + cb + i * 4] =
                    make_uint4(f2tf(t.x), f2tf(t.y), f2tf(t.z), f2tf(t.w));
            }
        }
        {
            const int hb = (tid & 15) * 4;
            #pragma unroll
            for (int p = 0; p < 8; p++) {
                const int kl = (tid >> 4) + p * 8;
                float4 t = *(const float4*)(Vh + base + (size_t)(k0 + kl) * HD + hb);
                sm[VT_OFF + (uint32_t)(hb + 0) * VPITCH + kl] = f2tf(t.x);
                sm[VT_OFF + (uint32_t)(hb + 1) * VPITCH + kl] = f2tf(t.y);
                sm[VT_OFF + (uint32_t)(hb + 2) * VPITCH + kl] = f2tf(t.z);
                sm[VT_OFF + (uint32_t)(hb + 3) * VPITCH + kl] = f2tf(t.w);
            }
        }
        __syncthreads();

        float sacc[8][4];
        #pragma unroll
        for (int nf = 0; nf < 8; nf++)
            #pragma unroll
            for (int t = 0; t < 4; t++) sacc[nf][t] = 0.f;
        #pragma unroll
        for (int kf = 0; kf < 8; kf++) {
            #pragma unroll
            for (int nf = 0; nf < 8; nf++) {
                const uint32_t* bp = sm + KS_OFF + (uint32_t)(nf * 8 + g) * KPITCH + kf * 8;
                mma8(sacc[nf], qa[kf], bp[tig], bp[tig + 4]);
            }
        }

        if (kt == qt) {
            #pragma unroll
            for (int nf = 0; nf < 8; nf++) {
                const int c0 = nf * 8 + tig * 2;
                const int rA = m0 + g, rB = m0 + g + 8;
                if (c0 > rA)     sacc[nf][0] = -1e30f;
                if (c0 + 1 > rA) sacc[nf][1] = -1e30f;
                if (c0 > rB)     sacc[nf][2] = -1e30f;
                if (c0 + 1 > rB) sacc[nf][3] = -1e30f;
            }
        }

        float tm0 = -1e30f, tm1 = -1e30f;
        #pragma unroll
        for (int nf = 0; nf < 8; nf++) {
            tm0 = fmaxf(tm0, fmaxf(sacc[nf][0], sacc[nf][1]));
            tm1 = fmaxf(tm1, fmaxf(sacc[nf][2], sacc[nf][3]));
        }
        tm0 = fmaxf(tm0, __shfl_xor_sync(0xffffffffu, tm0, 1));
        tm0 = fmaxf(tm0, __shfl_xor_sync(0xffffffffu, tm0, 2));
        tm1 = fmaxf(tm1, __shfl_xor_sync(0xffffffffu, tm1, 1));
        tm1 = fmaxf(tm1, __shfl_xor_sync(0xffffffffu, tm1, 2));
        const float mn0 = fmaxf(mr0, tm0), mn1 = fmaxf(mr1, tm1);
        const float al0 = __expf(mr0 - mn0), al1 = __expf(mr1 - mn1);
        mr0 = mn0; mr1 = mn1;
        l0 *= al0; l1 *= al1;
        #pragma unroll
        for (int nf = 0; nf < 8; nf++) {
            o[nf][0] *= al0; o[nf][1] *= al0;
            o[nf][2] *= al1; o[nf][3] *= al1;
        }
        #pragma unroll
        for (int nf = 0; nf < 8; nf++) {
            const float e0 = __expf(sacc[nf][0] - mn0);
            const float e1 = __expf(sacc[nf][1] - mn0);
            const float e2 = __expf(sacc[nf][2] - mn1);
            const float e3 = __expf(sacc[nf][3] - mn1);
            l0 += e0 + e1; l1 += e2 + e3;
            sacc[nf][0] = e0; sacc[nf][1] = e1;
            sacc[nf][2] = e2; sacc[nf][3] = e3;
        }

        const int sl0 = (lane & ~3) | (tig >> 1);
        const int sl2 = sl0 + 2;
        const bool odd = (tig & 1) != 0;
        #pragma unroll
        for (int kf = 0; kf < 8; kf++) {
            const float e0 = sacc[kf][0], e1 = sacc[kf][1];
            const float e2 = sacc[kf][2], e3 = sacc[kf][3];
            const float x00 = __shfl_sync(0xffffffffu, e0, sl0);
            const float x10 = __shfl_sync(0xffffffffu, e1, sl0);
            const float x02 = __shfl_sync(0xffffffffu, e0, sl2);
            const float x12 = __shfl_sync(0xffffffffu, e1, sl2);
            const float x20 = __shfl_sync(0xffffffffu, e2, sl0);
            const float x30 = __shfl_sync(0xffffffffu, e3, sl0);
            const float x22 = __shfl_sync(0xffffffffu, e2, sl2);
            const float x32 = __shfl_sync(0xffffffffu, e3, sl2);
            uint32_t pa[4];
            pa[0] = f2tf(odd ? x10 : x00);
            pa[1] = f2tf(odd ? x30 : x20);
            pa[2] = f2tf(odd ? x12 : x02);
            pa[3] = f2tf(odd ? x32 : x22);
            #pragma unroll
            for (int nf = 0; nf < 8; nf++) {
                const uint32_t* bp = sm + VT_OFF + (uint32_t)(nf * 8 + g) * VPITCH + kf * 8;
                mma8(o[nf], pa, bp[tig], bp[tig + 4]);
            }
        }
        __syncthreads();
    }

    l0 += __shfl_xor_sync(0xffffffffu, l0, 1);
    l0 += __shfl_xor_sync(0xffffffffu, l0, 2);
    l1 += __shfl_xor_sync(0xffffffffu, l1, 1);
    l1 += __shfl_xor_sync(0xffffffffu, l1, 2);
    const float i0 = 1.f / l0, i1 = 1.f / l1;
    const int r0 = q0 + m0 + g;
    #pragma unroll
    for (int nf = 0; nf < 8; nf++) {
        const int col = h * HD + nf * 8 + tig * 2;
        *(float2*)(feats + ((size_t)(b * SLEN + r0)) * DMODEL + col) =
            make_float2(o[nf][0] * i0, o[nf][1] * i0);
        *(float2*)(feats + ((size_t)(b * SLEN + r0 + 8)) * DMODEL + col) =
            make_float2(o[nf][2] * i1, o[nf][3] * i1);
    }
}

// ==================== launch ====================
extern "C" void kernel_launch(void* const* d_in, const int* in_sizes, int n_in,
                              void* d_out, int out_size)
{
    const float* q  = (const float*)d_in[0];
    const float* k  = (const float*)d_in[1];
    const float* v  = (const float*)d_in[2];
    // d_in[3] = mask (always causal triu(k=1); handled analytically)
    const float* Wq = (const float*)d_in[4];
    const float* bq = (const float*)d_in[5];
    const float* Wk = (const float*)d_in[6];
    const float* bk = (const float*)d_in[7];
    const float* Wv = (const float*)d_in[8];
    const float* bv = (const float*)d_in[9];
    const float* Wo = (const float*)d_in[10];
    const float* bo = (const float*)d_in[11];

    float *qh, *kh, *vh, *feats;
    cudaGetSymbolAddress((void**)&qh, g_qh);
    cudaGetSymbolAddress((void**)&kh, g_kh);
    cudaGetSymbolAddress((void**)&vh, g_vh);
    cudaGetSymbolAddress((void**)&feats, g_feats);

    cudaFuncSetAttribute(mma_gemm_kernel,
                         cudaFuncAttributeMaxDynamicSharedMemorySize, GEMM_SMEM);
    cudaFuncSetAttribute(attn_mma_kernel,
                         cudaFuncAttributeMaxDynamicSharedMemorySize, ATT_SMEM_BYTES);

    dim3 gg(DMODEL / 128, MROWS / 128);   // (6, 64)
    mma_gemm_kernel<<<gg, 256, GEMM_SMEM>>>(q, Wq, bq, qh, 1);
    mma_gemm_kernel<<<gg, 256, GEMM_SMEM>>>(k, Wk, bk, kh, 1);
    mma_gemm_kernel<<<gg, 256, GEMM_SMEM>>>(v, Wv, bv, vh, 1);

    attn_mma_kernel<<<dim3(SLEN / 64, BATCH * NH), 128, ATT_SMEM_BYTES>>>(qh, kh, vh, feats);

    mma_gemm_kernel<<<gg, 256, GEMM_SMEM>>>(feats, Wo, bo, (float*)d_out, 0);
}

// round 6
// speedup vs baseline: 3.9772x; 1.3036x over previous
#include <cuda_runtime.h>
#include <math.h>
#include <stdint.h>

// Problem constants
#define BATCH 2
#define SLEN  4096
#define DMODEL 768
#define NH    12
#define HD    64
#define MROWS (BATCH * SLEN)        // 8192

// ---------------- scratch (device globals; allocation-free) ----------------
__device__ float g_qh[BATCH * NH * SLEN * HD];   // [B,H,S,HD]
__device__ float g_kh[BATCH * NH * SLEN * HD];
__device__ float g_vh[BATCH * NH * SLEN * HD];
__device__ float g_feats[BATCH * SLEN * DMODEL]; // [B,S,D]

// ==================== helpers ====================
__device__ __forceinline__ uint32_t f2tf(float x) {
    uint32_t r;
    asm("cvt.rna.tf32.f32 %0, %1;" : "=r"(r) : "f"(x));
    return r;
}
// D = A(16x8, row) @ B(8x8, col) + D, tf32 inputs, f32 accum
__device__ __forceinline__ void mma8(float* c, const uint32_t* a,
                                     uint32_t b0, uint32_t b1) {
    asm volatile(
        "mma.sync.aligned.m16n8k8.row.col.f32.tf32.tf32.f32 "
        "{%0,%1,%2,%3}, {%4,%5,%6,%7}, {%8,%9}, {%0,%1,%2,%3};"
        : "+f"(c[0]), "+f"(c[1]), "+f"(c[2]), "+f"(c[3])
        : "r"(a[0]), "r"(a[1]), "r"(a[2]), "r"(a[3]), "r"(b0), "r"(b1));
}

// ==================== tf32 mma.sync GEMM: C = X @ W^T + bias ====================
#define TBK 32
#define APITCH 36
#define STAGE_WORDS (128 * APITCH)                 // 4608 words
#define GEMM_SMEM (4 * STAGE_WORDS * 4)            // 73728 B

__global__ __launch_bounds__(256)
void mma_gemm_kernel(const float* __restrict__ A, const float* __restrict__ W,
                     const float* __restrict__ bias, float* __restrict__ C, int mode)
{
    extern __shared__ uint32_t sm[];
    uint32_t* AsBase = sm;                       // [2][STAGE_WORDS]
    uint32_t* BsBase = sm + 2 * STAGE_WORDS;     // [2][STAGE_WORDS]

    const int tid  = threadIdx.x;
    const int lane = tid & 31, wid = tid >> 5;
    const int g = lane >> 2, tig = lane & 3;
    const int wm = wid >> 2, wn = wid & 3;       // 2 x 4 warp grid
    const int bm = blockIdx.y * 128, bn = blockIdx.x * 128;

    const int lr = tid >> 3;                     // 0..31
    const int lc = (tid & 7) * 4;                // 0,4,...,28
    const float* Ap = A + (size_t)(bm + lr) * DMODEL + lc;
    const float* Wp = W + (size_t)(bn + lr) * DMODEL + lc;

    float acc[4][4][4];
    #pragma unroll
    for (int i = 0; i < 4; i++)
        #pragma unroll
        for (int j = 0; j < 4; j++)
            #pragma unroll
            for (int t = 0; t < 4; t++) acc[i][j][t] = 0.f;

    float4 ra[4], rb[4];
    #pragma unroll
    for (int i = 0; i < 4; i++) {
        ra[i] = *(const float4*)(Ap + (size_t)i * 32 * DMODEL);
        rb[i] = *(const float4*)(Wp + (size_t)i * 32 * DMODEL);
    }
    #pragma unroll
    for (int i = 0; i < 4; i++) {
        const uint32_t idx = (uint32_t)(lr + 32 * i) * APITCH + lc;
        *(uint4*)&AsBase[idx] = make_uint4(f2tf(ra[i].x), f2tf(ra[i].y), f2tf(ra[i].z), f2tf(ra[i].w));
        *(uint4*)&BsBase[idx] = make_uint4(f2tf(rb[i].x), f2tf(rb[i].y), f2tf(rb[i].z), f2tf(rb[i].w));
    }
    __syncthreads();

    const int KT = DMODEL / TBK;                 // 24
    for (int kt = 0; kt < KT; kt++) {
        const int s = kt & 1;
        const uint32_t* Sa = AsBase + s * STAGE_WORDS;
        const uint32_t* Sb = BsBase + s * STAGE_WORDS;

        if (kt + 1 < KT) {
            const float* ap = Ap + (size_t)(kt + 1) * TBK;
            const float* wp = Wp + (size_t)(kt + 1) * TBK;
            #pragma unroll
            for (int i = 0; i < 4; i++) {
                ra[i] = *(const float4*)(ap + (size_t)i * 32 * DMODEL);
                rb[i] = *(const float4*)(wp + (size_t)i * 32 * DMODEL);
            }
        }

        #pragma unroll
        for (int kk = 0; kk < 4; kk++) {
            const int k0 = kk * 8;
            uint32_t af[4][4];
            #pragma unroll
            for (int mf = 0; mf < 4; mf++) {
                const uint32_t* bp = Sa + (uint32_t)(wm * 64 + mf * 16) * APITCH + k0;
                af[mf][0] = bp[(uint32_t)g * APITCH + tig];
                af[mf][1] = bp[(uint32_t)(g + 8) * APITCH + tig];
                af[mf][2] = bp[(uint32_t)g * APITCH + tig + 4];
                af[mf][3] = bp[(uint32_t)(g + 8) * APITCH + tig + 4];
            }
            uint32_t bf[4][2];
            #pragma unroll
            for (int nf = 0; nf < 4; nf++) {
                const uint32_t* bp = Sb + (uint32_t)(wn * 32 + nf * 8 + g) * APITCH + k0;
                bf[nf][0] = bp[tig];
                bf[nf][1] = bp[tig + 4];
            }
            #pragma unroll
            for (int mf = 0; mf < 4; mf++)
                #pragma unroll
                for (int nf = 0; nf < 4; nf++)
                    mma8(acc[mf][nf], af[mf], bf[nf][0], bf[nf][1]);
        }

        if (kt + 1 < KT) {
            __syncthreads();
            const int s1 = s ^ 1;
            #pragma unroll
            for (int i = 0; i < 4; i++) {
                const uint32_t idx = (uint32_t)(lr + 32 * i) * APITCH + lc;
                *(uint4*)&AsBase[s1 * STAGE_WORDS + idx] =
                    make_uint4(f2tf(ra[i].x), f2tf(ra[i].y), f2tf(ra[i].z), f2tf(ra[i].w));
                *(uint4*)&BsBase[s1 * STAGE_WORDS + idx] =
                    make_uint4(f2tf(rb[i].x), f2tf(rb[i].y), f2tf(rb[i].z), f2tf(rb[i].w));
            }
            __syncthreads();
        }
    }

    // epilogue
    #pragma unroll
    for (int mf = 0; mf < 4; mf++) {
        const int r0 = bm + wm * 64 + mf * 16 + g;
        #pragma unroll
        for (int nf = 0; nf < 4; nf++) {
            const int c = bn + wn * 32 + nf * 8 + tig * 2;
            const float b0 = bias[c], b1 = bias[c + 1];
            float2 v0 = make_float2(acc[mf][nf][0] + b0, acc[mf][nf][1] + b1);
            float2 v1 = make_float2(acc[mf][nf][2] + b0, acc[mf][nf][3] + b1);
            if (mode == 0) {
                *(float2*)(C + (size_t)r0 * DMODEL + c) = v0;
                *(float2*)(C + (size_t)(r0 + 8) * DMODEL + c) = v1;
            } else {
                const int h = c >> 6, hd = c & (HD - 1);
                const int bb0 = r0 >> 12, s0r = r0 & (SLEN - 1);
                *(float2*)(C + (((size_t)(bb0 * NH + h)) * SLEN + s0r) * HD + hd) = v0;
                const int r1 = r0 + 8;
                const int bb1 = r1 >> 12, s1r = r1 & (SLEN - 1);
                *(float2*)(C + (((size_t)(bb1 * NH + h)) * SLEN + s1r) * HD + hd) = v1;
            }
        }
    }
}

// ==================== flash attention with mma.sync (tf32) ====================
// Block: 128 thr (4 warps). 128 q-rows/block, 32 q-rows/warp, 64-key tiles.
#define QP 68
#define KP 68
#define VP 69
#define QS_OFF 0
#define KS_OFF (128 * QP)                     // 8704
#define VT_OFF (KS_OFF + 64 * KP)             // 13056
#define ATT_SMEM_BYTES ((VT_OFF + 64 * VP) * 4)   // 69888

__global__ __launch_bounds__(128)
void attn_mma_kernel(const float* __restrict__ Qh, const float* __restrict__ Kh,
                     const float* __restrict__ Vh, float* __restrict__ feats)
{
    extern __shared__ uint32_t sm[];
    const int tid = threadIdx.x, lane = tid & 31, w = tid >> 5;
    const int g = lane >> 2, tig = lane & 3;
    const int bh = blockIdx.y;
    const int qt = gridDim.x - 1 - blockIdx.x;     // LPT: heavy tiles first
    const int q0 = qt * 128;
    const int b = bh / NH, h = bh % NH;
    const size_t base = (size_t)bh * SLEN * HD;
    const int m0 = w * 32;

    // ---- stage Q tile (128 x 64), scaled + tf32 ----
    {
        const float4* src = (const float4*)(Qh + base + (size_t)(q0 + tid) * HD);
        #pragma unroll
        for (int i = 0; i < 16; i++) {
            float4 t = src[i];
            *(uint4*)&sm[QS_OFF + (uint32_t)tid * QP + i * 4] =
                make_uint4(f2tf(t.x * 0.125f), f2tf(t.y * 0.125f),
                           f2tf(t.z * 0.125f), f2tf(t.w * 0.125f));
        }
    }
    __syncthreads();

    // Q fragments resident: 2 mf blocks x 8 kf
    uint32_t qa[2][8][4];
    #pragma unroll
    for (int mf = 0; mf < 2; mf++) {
        const uint32_t rbase = (uint32_t)(m0 + mf * 16);
        #pragma unroll
        for (int kf = 0; kf < 8; kf++) {
            qa[mf][kf][0] = sm[QS_OFF + (rbase + g) * QP + kf * 8 + tig];
            qa[mf][kf][1] = sm[QS_OFF + (rbase + g + 8) * QP + kf * 8 + tig];
            qa[mf][kf][2] = sm[QS_OFF + (rbase + g) * QP + kf * 8 + tig + 4];
            qa[mf][kf][3] = sm[QS_OFF + (rbase + g + 8) * QP + kf * 8 + tig + 4];
        }
    }

    float o[2][8][4];
    #pragma unroll
    for (int mf = 0; mf < 2; mf++)
        #pragma unroll
        for (int nf = 0; nf < 8; nf++)
            #pragma unroll
            for (int t = 0; t < 4; t++) o[mf][nf][t] = 0.f;
    float mr[2][2] = {{-INFINITY, -INFINITY}, {-INFINITY, -INFINITY}};
    float l[2][2] = {{0.f, 0.f}, {0.f, 0.f}};

    const int ntiles = 2 * qt + 2;
    for (int kt = 0; kt < ntiles; kt++) {
        const int k0 = kt * 64;
        // ---- load K tile (64 x 64) ----
        {
            const int r = tid >> 1;
            const int cb = (tid & 1) * 32;
            const float4* src = (const float4*)(Kh + base + (size_t)(k0 + r) * HD + cb);
            #pragma unroll
            for (int i = 0; i < 8; i++) {
                float4 t = src[i];
                *(uint4*)&sm[KS_OFF + (uint32_t)r * KP + cb + i * 4] =
                    make_uint4(f2tf(t.x), f2tf(t.y), f2tf(t.z), f2tf(t.w));
            }
        }
        // ---- load V tile transposed: VT[hd][key] ----
        {
            const int hb = (tid & 15) * 4;
            #pragma unroll
            for (int p = 0; p < 8; p++) {
                const int kl = (tid >> 4) + p * 8;
                float4 t = *(const float4*)(Vh + base + (size_t)(k0 + kl) * HD + hb);
                sm[VT_OFF + (uint32_t)(hb + 0) * VP + kl] = f2tf(t.x);
                sm[VT_OFF + (uint32_t)(hb + 1) * VP + kl] = f2tf(t.y);
                sm[VT_OFF + (uint32_t)(hb + 2) * VP + kl] = f2tf(t.z);
                sm[VT_OFF + (uint32_t)(hb + 3) * VP + kl] = f2tf(t.w);
            }
        }
        __syncthreads();

        const bool active = (k0 <= q0 + m0 + 31);   // warp-uniform
        if (active) {
            // ---- S = Q @ K^T : 32 x 64 per warp ----
            float sacc[2][8][4];
            #pragma unroll
            for (int mf = 0; mf < 2; mf++)
                #pragma unroll
                for (int nf = 0; nf < 8; nf++)
                    #pragma unroll
                    for (int t = 0; t < 4; t++) sacc[mf][nf][t] = 0.f;
            #pragma unroll
            for (int kf = 0; kf < 8; kf++) {
                #pragma unroll
                for (int nf = 0; nf < 8; nf++) {
                    const uint32_t* bp = sm + KS_OFF + (uint32_t)(nf * 8 + g) * KP + kf * 8;
                    const uint32_t b0 = bp[tig], b1 = bp[tig + 4];
                    mma8(sacc[0][nf], qa[0][kf], b0, b1);
                    mma8(sacc[1][nf], qa[1][kf], b0, b1);
                }
            }

            // ---- causal mask (only near diagonal) ----
            if (k0 + 63 > q0 + m0) {
                #pragma unroll
                for (int mf = 0; mf < 2; mf++) {
                    const int rA = q0 + m0 + mf * 16 + g;
                    const int rB = rA + 8;
                    #pragma unroll
                    for (int nf = 0; nf < 8; nf++) {
                        const int c0 = k0 + nf * 8 + tig * 2;
                        if (c0 > rA)     sacc[mf][nf][0] = -1e30f;
                        if (c0 + 1 > rA) sacc[mf][nf][1] = -1e30f;
                        if (c0 > rB)     sacc[mf][nf][2] = -1e30f;
                        if (c0 + 1 > rB) sacc[mf][nf][3] = -1e30f;
                    }
                }
            }

            // ---- online softmax per mf (rows g, g+8) ----
            #pragma unroll
            for (int mf = 0; mf < 2; mf++) {
                float tm0 = -1e30f, tm1 = -1e30f;
                #pragma unroll
                for (int nf = 0; nf < 8; nf++) {
                    tm0 = fmaxf(tm0, fmaxf(sacc[mf][nf][0], sacc[mf][nf][1]));
                    tm1 = fmaxf(tm1, fmaxf(sacc[mf][nf][2], sacc[mf][nf][3]));
                }
                tm0 = fmaxf(tm0, __shfl_xor_sync(0xffffffffu, tm0, 1));
                tm0 = fmaxf(tm0, __shfl_xor_sync(0xffffffffu, tm0, 2));
                tm1 = fmaxf(tm1, __shfl_xor_sync(0xffffffffu, tm1, 1));
                tm1 = fmaxf(tm1, __shfl_xor_sync(0xffffffffu, tm1, 2));
                const float mn0 = fmaxf(mr[mf][0], tm0), mn1 = fmaxf(mr[mf][1], tm1);
                const float al0 = __expf(mr[mf][0] - mn0), al1 = __expf(mr[mf][1] - mn1);
                mr[mf][0] = mn0; mr[mf][1] = mn1;
                l[mf][0] *= al0; l[mf][1] *= al1;
                #pragma unroll
                for (int nf = 0; nf < 8; nf++) {
                    o[mf][nf][0] *= al0; o[mf][nf][1] *= al0;
                    o[mf][nf][2] *= al1; o[mf][nf][3] *= al1;
                }
                #pragma unroll
                for (int nf = 0; nf < 8; nf++) {
                    const float e0 = __expf(sacc[mf][nf][0] - mn0);
                    const float e1 = __expf(sacc[mf][nf][1] - mn0);
                    const float e2 = __expf(sacc[mf][nf][2] - mn1);
                    const float e3 = __expf(sacc[mf][nf][3] - mn1);
                    l[mf][0] += e0 + e1; l[mf][1] += e2 + e3;
                    sacc[mf][nf][0] = e0; sacc[mf][nf][1] = e1;
                    sacc[mf][nf][2] = e2; sacc[mf][nf][3] = e3;
                }
            }

            // ---- O += P @ V ----
            const int sl0 = (lane & ~3) | (tig >> 1);
            const int sl2 = sl0 + 2;
            const bool odd = (tig & 1) != 0;
            #pragma unroll
            for (int kf = 0; kf < 8; kf++) {
                uint32_t pa[2][4];
                #pragma unroll
                for (int mf = 0; mf < 2; mf++) {
                    const float e0 = sacc[mf][kf][0], e1 = sacc[mf][kf][1];
                    const float e2 = sacc[mf][kf][2], e3 = sacc[mf][kf][3];
                    const float x00 = __shfl_sync(0xffffffffu, e0, sl0);
                    const float x10 = __shfl_sync(0xffffffffu, e1, sl0);
                    const float x02 = __shfl_sync(0xffffffffu, e0, sl2);
                    const float x12 = __shfl_sync(0xffffffffu, e1, sl2);
                    const float x20 = __shfl_sync(0xffffffffu, e2, sl0);
                    const float x30 = __shfl_sync(0xffffffffu, e3, sl0);
                    const float x22 = __shfl_sync(0xffffffffu, e2, sl2);
                    const float x32 = __shfl_sync(0xffffffffu, e3, sl2);
                    pa[mf][0] = f2tf(odd ? x10 : x00);
                    pa[mf][1] = f2tf(odd ? x30 : x20);
                    pa[mf][2] = f2tf(odd ? x12 : x02);
                    pa[mf][3] = f2tf(odd ? x32 : x22);
                }
                #pragma unroll
                for (int nf = 0; nf < 8; nf++) {
                    const uint32_t* bp = sm + VT_OFF + (uint32_t)(nf * 8 + g) * VP + kf * 8;
                    const uint32_t b0 = bp[tig], b1 = bp[tig + 4];
                    mma8(o[0][nf], pa[0], b0, b1);
                    mma8(o[1][nf], pa[1], b0, b1);
                }
            }
        }
        __syncthreads();
    }

    // ---- finalize ----
    #pragma unroll
    for (int mf = 0; mf < 2; mf++) {
        float l0 = l[mf][0], l1 = l[mf][1];
        l0 += __shfl_xor_sync(0xffffffffu, l0, 1);
        l0 += __shfl_xor_sync(0xffffffffu, l0, 2);
        l1 += __shfl_xor_sync(0xffffffffu, l1, 1);
        l1 += __shfl_xor_sync(0xffffffffu, l1, 2);
        const float i0 = 1.f / l0, i1 = 1.f / l1;
        const int r0 = q0 + m0 + mf * 16 + g;
        #pragma unroll
        for (int nf = 0; nf < 8; nf++) {
            const int col = h * HD + nf * 8 + tig * 2;
            *(float2*)(feats + ((size_t)(b * SLEN + r0)) * DMODEL + col) =
                make_float2(o[mf][nf][0] * i0, o[mf][nf][1] * i0);
            *(float2*)(feats + ((size_t)(b * SLEN + r0 + 8)) * DMODEL + col) =
                make_float2(o[mf][nf][2] * i1, o[mf][nf][3] * i1);
        }
    }
}

// ==================== launch ====================
extern "C" void kernel_launch(void* const* d_in, const int* in_sizes, int n_in,
                              void* d_out, int out_size)
{
    const float* q  = (const float*)d_in[0];
    const float* k  = (const float*)d_in[1];
    const float* v  = (const float*)d_in[2];
    // d_in[3] = mask (always causal triu(k=1); handled analytically)
    const float* Wq = (const float*)d_in[4];
    const float* bq = (const float*)d_in[5];
    const float* Wk = (const float*)d_in[6];
    const float* bk = (const float*)d_in[7];
    const float* Wv = (const float*)d_in[8];
    const float* bv = (const float*)d_in[9];
    const float* Wo = (const float*)d_in[10];
    const float* bo = (const float*)d_in[11];

    float *qh, *kh, *vh, *feats;
    cudaGetSymbolAddress((void**)&qh, g_qh);
    cudaGetSymbolAddress((void**)&kh, g_kh);
    cudaGetSymbolAddress((void**)&vh, g_vh);
    cudaGetSymbolAddress((void**)&feats, g_feats);

    cudaFuncSetAttribute(mma_gemm_kernel,
                         cudaFuncAttributeMaxDynamicSharedMemorySize, GEMM_SMEM);
    cudaFuncSetAttribute(attn_mma_kernel,
                         cudaFuncAttributeMaxDynamicSharedMemorySize, ATT_SMEM_BYTES);

    dim3 gg(DMODEL / 128, MROWS / 128);   // (6, 64)
    mma_gemm_kernel<<<gg, 256, GEMM_SMEM>>>(q, Wq, bq, qh, 1);
    mma_gemm_kernel<<<gg, 256, GEMM_SMEM>>>(k, Wk, bk, kh, 1);
    mma_gemm_kernel<<<gg, 256, GEMM_SMEM>>>(v, Wv, bv, vh, 1);

    attn_mma_kernel<<<dim3(SLEN / 128, BATCH * NH), 128, ATT_SMEM_BYTES>>>(qh, kh, vh, feats);

    mma_gemm_kernel<<<gg, 256, GEMM_SMEM>>>(feats, Wo, bo, (float*)d_out, 0);
}